// round 17
// baseline (speedup 1.0000x reference)
#include <cuda_runtime.h>
#include <cuda_fp16.h>
#include <math.h>

#define B_  4
#define S_  2048
#define D_  1024
#define H_  16
#define DH_ 64
#define M_  (B_*S_)          // 8192 rows

typedef unsigned long long u64;
typedef unsigned int u32;

// ---------------- helpers ----------------------------------------
__device__ __forceinline__ u32 smem_u32(const void* p) {
    u32 a;
    asm("{ .reg .u64 t; cvta.to.shared.u64 t, %1; cvt.u32.u64 %0, t; }"
        : "=r"(a) : "l"(p));
    return a;
}
__device__ __forceinline__ void ldmx4(u32* r, u32 addr) {
    asm volatile("ldmatrix.sync.aligned.m8n8.x4.shared.b16 {%0,%1,%2,%3}, [%4];"
                 : "=r"(r[0]), "=r"(r[1]), "=r"(r[2]), "=r"(r[3]) : "r"(addr));
}
__device__ __forceinline__ void ldmx4t(u32* r, u32 addr) {
    asm volatile("ldmatrix.sync.aligned.m8n8.x4.trans.shared.b16 {%0,%1,%2,%3}, [%4];"
                 : "=r"(r[0]), "=r"(r[1]), "=r"(r[2]), "=r"(r[3]) : "r"(addr));
}
__device__ __forceinline__ void mma_f16(float* c, const u32* a, u32 b0, u32 b1) {
    asm volatile(
        "mma.sync.aligned.m16n8k16.row.col.f32.f16.f16.f32 "
        "{%0,%1,%2,%3}, {%4,%5,%6,%7}, {%8,%9}, {%0,%1,%2,%3};"
        : "+f"(c[0]), "+f"(c[1]), "+f"(c[2]), "+f"(c[3])
        : "r"(a[0]), "r"(a[1]), "r"(a[2]), "r"(a[3]), "r"(b0), "r"(b1));
}
// pack two floats -> f16x2 {lo, hi}
__device__ __forceinline__ u32 pkhf(float lo, float hi) {
    u32 r; asm("cvt.rn.f16x2.f32 %0, %2, %1;" : "=r"(r) : "f"(lo), "f"(hi)); return r;
}
__device__ __forceinline__ float ex2f(float x) {
    float y; asm("ex2.approx.ftz.f32 %0, %1;" : "=f"(y) : "f"(x)); return y;
}
__device__ __forceinline__ void cpa16(u32 dst, const void* src) {
    asm volatile("cp.async.cg.shared.global [%0], [%1], 16;"
                 :: "r"(dst), "l"(__cvta_generic_to_global(src)) : "memory");
}
__device__ __forceinline__ void cp_commit() {
    asm volatile("cp.async.commit_group;" ::: "memory");
}
__device__ __forceinline__ void cp_wait0() {
    asm volatile("cp.async.wait_group 0;" ::: "memory");
}

// ---------------- scratch (no allocations allowed) ----------------
__device__ float g_res[(size_t)M_*D_];           // pre-layernorm
__device__ __half g_x [(size_t)M_*D_];           // x in fp16
__device__ __half g_wt[(size_t)4096*1024];       // [n][k]: 0-3071 WQKV^T, 3072-4095 WO^T
__device__ __half g_q [(size_t)B_*H_*S_*DH_];    // [B,H,S,DH], q pre-scaled 0.125*log2e
__device__ __half g_k [(size_t)B_*H_*S_*DH_];
__device__ __half g_v [(size_t)B_*H_*S_*DH_];
__device__ __half g_cx[(size_t)M_*D_];           // ctx [m][k] fp16

// =================================================================
// Prep: convert x to fp16
// =================================================================
__global__ __launch_bounds__(256) void cvt_x(const float* __restrict__ x)
{
    size_t i = (size_t)blockIdx.x * 1024 + threadIdx.x * 4;
    float4 v = *(const float4*)(x + i);
    *(u32*)(g_x + i)     = pkhf(v.x, v.y);
    *(u32*)(g_x + i + 2) = pkhf(v.z, v.w);
}

// =================================================================
// Prep: transpose W (k-major -> n-major) to fp16
// =================================================================
__global__ void wt_t(const float* __restrict__ wq, const float* __restrict__ wk,
                     const float* __restrict__ wv, const float* __restrict__ wo)
{
    __shared__ float tile[32][33];
    const int k0 = blockIdx.x * 32, n0 = blockIdx.y * 32;
    const int mat = n0 >> 10, c0 = n0 & 1023;
    const float* __restrict__ W = (mat == 0) ? wq : (mat == 1) ? wk : (mat == 2) ? wv : wo;
    const int tx = threadIdx.x, ty = threadIdx.y;
#pragma unroll
    for (int i = 0; i < 4; i++)
        tile[ty + i * 8][tx] = W[(size_t)(k0 + ty + i * 8) * 1024 + c0 + tx];
    __syncthreads();
#pragma unroll
    for (int i = 0; i < 4; i++) {
        int rr = ty + i * 8;
        g_wt[(size_t)(n0 + rr) * 1024 + k0 + tx] = __float2half(tile[tx][rr]);
    }
}

// =================================================================
// HMMA GEMM core (fp16 single-term, cp.async double-buffered):
// C(128x128 f32) = A @ B^T ; A [m][k], B [n][k], both fp16.
// =================================================================
#define SK 40                       // smem row stride in fp16 (80B)
#define TILE_BYTES  (128 * SK * 2)  // 10240
#define STAGE_BYTES (2 * TILE_BYTES)

__device__ __forceinline__ void gemm_prefetch(
    const __half* __restrict__ A, const __half* __restrict__ B,
    int m0, int n0row, int k0, u32 st, int row, int half)
{
    const u32 cpo = (u32)(row * SK + half * 16) * 2;
    const size_t ga = (size_t)(m0 + row) * 1024 + k0 + half * 16;
    const size_t gn = (size_t)(n0row + row) * 1024 + k0 + half * 16;
    cpa16(st + cpo,                   A + ga);
    cpa16(st + cpo + 16,              A + ga + 8);
    cpa16(st + TILE_BYTES + cpo,      B + gn);
    cpa16(st + TILE_BYTES + cpo + 16, B + gn + 8);
    cp_commit();
}

__device__ __forceinline__ void hmma_core(
    const __half* __restrict__ A, const __half* __restrict__ B,
    int m0, int n0row, __half* sm, float acc[2][8][4])
{
    const int tid = threadIdx.x;
    const int lane = tid & 31, wid = tid >> 5;
    const int wm = wid >> 1, wn = wid & 1;
    const int lrow = lane & 15, lcol = (lane >> 4) << 3;
    const int row = tid >> 1, half = tid & 1;

    const u32 sb = smem_u32(sm);
    const u32 aoff = (u32)((wm * 32 + lrow) * SK + lcol) * 2;
    const u32 boff = (u32)((wn * 64 + lrow) * SK + lcol) * 2;

    gemm_prefetch(A, B, m0, n0row, 0, sb, row, half);

    for (int c = 0; c < 32; ++c) {
        cp_wait0();
        __syncthreads();
        if (c + 1 < 32)
            gemm_prefetch(A, B, m0, n0row, (c + 1) * 32,
                          sb + ((c + 1) & 1) * STAGE_BYTES, row, half);

        const u32 st = sb + (c & 1) * STAGE_BYTES;
        const u32 aB = st + aoff, bB = st + TILE_BYTES + boff;
#pragma unroll
        for (int ks = 0; ks < 2; ++ks) {
            const u32 kofs = ks * 32;
            u32 a2[2][4];
            ldmx4(a2[0], aB + kofs);
            ldmx4(a2[1], aB + 16 * SK * 2 + kofs);
#pragma unroll
            for (int hf = 0; hf < 2; ++hf) {
                const u32 ho = hf * 32 * SK * 2;
                u32 b2[2][4];
                ldmx4(b2[0], bB + ho + kofs);
                ldmx4(b2[1], bB + ho + 16 * SK * 2 + kofs);
#pragma unroll
                for (int mi = 0; mi < 2; ++mi)
#pragma unroll
                    for (int jj = 0; jj < 4; ++jj) {
                        const int jb = jj >> 1, sl = jj & 1;
                        mma_f16(acc[mi][hf * 4 + jj], a2[mi],
                                b2[jb][sl], b2[jb][sl + 2]);
                    }
            }
        }
    }
}

// =================================================================
// QKV GEMM: write q/k/v fp16 [B,H,S,DH]; q scaled 0.125*log2(e)
// =================================================================
__global__ __launch_bounds__(256, 2) void qkv_hmma()
{
    extern __shared__ __half dynsm[];
    const int m0 = blockIdx.x * 128;
    const int n0 = blockIdx.y * 128;          // 0..3071

    float acc[2][8][4] = {};
    hmma_core(g_x, g_wt, m0, n0, dynsm, acc);

    const int tid = threadIdx.x, lane = tid & 31, wid = tid >> 5;
    const int wm = wid >> 1, wn = wid & 1;
    const int gid = lane >> 2, tig = lane & 3;
    const int which = n0 >> 10;
    __half* __restrict__ op = (which == 0) ? g_q : (which == 1) ? g_k : g_v;
    const float sc = (which == 0) ? 0.125f * 1.4426950408889634f : 1.0f;
    const int nl0 = (n0 & 1023) + wn * 64;

#pragma unroll
    for (int mi = 0; mi < 2; ++mi) {
        const int r = m0 + wm * 32 + mi * 16 + gid;
        const int b = r >> 11, s = r & (S_ - 1);
#pragma unroll
        for (int j = 0; j < 8; ++j) {
            const int nl = nl0 + j * 8 + tig * 2;
            const int h = nl >> 6, d = nl & 63;
            const size_t base = ((size_t)(b * H_ + h) * S_ + s) * DH_ + d;
            *(u32*)(op + base)           = pkhf(acc[mi][j][0] * sc, acc[mi][j][1] * sc);
            *(u32*)(op + base + 8 * DH_) = pkhf(acc[mi][j][2] * sc, acc[mi][j][3] * sc);
        }
    }
}

// =================================================================
// Output projection + residual: g_res = ctx @ W_O + x
// =================================================================
__global__ __launch_bounds__(256, 2) void proj_hmma(const float* __restrict__ x)
{
    extern __shared__ __half dynsm[];
    const int m0 = blockIdx.x * 128;
    const int n0 = blockIdx.y * 128;          // 0..1023

    float acc[2][8][4] = {};
    hmma_core(g_cx, g_wt, m0, n0 + 3072, dynsm, acc);

    const int tid = threadIdx.x, lane = tid & 31, wid = tid >> 5;
    const int wm = wid >> 1, wn = wid & 1;
    const int gid = lane >> 2, tig = lane & 3;
    const int nb = n0 + wn * 64;

#pragma unroll
    for (int mi = 0; mi < 2; ++mi) {
        const size_t r = m0 + wm * 32 + mi * 16 + gid;
#pragma unroll
        for (int j = 0; j < 8; ++j) {
            const size_t n = nb + j * 8 + tig * 2;
            float2 x0 = *(const float2*)(x + r * D_ + n);
            float2 x1 = *(const float2*)(x + (r + 8) * D_ + n);
            *(float2*)(g_res + r * D_ + n) =
                make_float2(acc[mi][j][0] + x0.x, acc[mi][j][1] + x0.y);
            *(float2*)(g_res + (r + 8) * D_ + n) =
                make_float2(acc[mi][j][2] + x1.x, acc[mi][j][3] + x1.y);
        }
    }
}

// =================================================================
// Flash attention (fp16 HMMA, causal, exp2 domain).
// Block = 128 queries / 4 warps; warp tile 32x64 (2 m-tiles) to
// double MMAs per ldmatrix. Q resident in smem; heavy blocks first.
// =================================================================
#define SKA 72

__global__ __launch_bounds__(128, 3) void attn_hmma()
{
    __shared__ __align__(16) __half smQ[128 * SKA];
    __shared__ __align__(16) __half smK[64 * SKA];
    __shared__ __align__(16) __half smV[64 * SKA];

    const int tid = threadIdx.x, lane = tid & 31, wm = tid >> 5;
    const int qt = gridDim.x - 1 - blockIdx.x;   // heavy blocks first
    const int bh = blockIdx.y;
    const int q0 = qt * 128;
    const size_t gb = (size_t)bh * S_ * DH_;
    const u32 sbQ = smem_u32(smQ), sbK = smem_u32(smK), sbV = smem_u32(smV);

    // ---- stage Q (128 rows x 64 fp16): one row per thread
    {
        const uint4* s = (const uint4*)(g_q + gb + (size_t)(q0 + tid) * DH_);
        uint4* d = (uint4*)(smQ + tid * SKA);
#pragma unroll
        for (int i = 0; i < 8; i++) d[i] = s[i];
    }
    __syncthreads();

    float o0[8][4] = {}, o1[8][4] = {};
    float mA0 = -1e30f, mB0 = -1e30f, mA1 = -1e30f, mB1 = -1e30f;
    float lA0 = 0.f, lB0 = 0.f, lA1 = 0.f, lB1 = 0.f;   // per-lane partials
    const int r0 = q0 + wm * 32 + (lane >> 2);           // m-tile 0 row
    const int r1 = r0 + 16;                              // m-tile 1 row
    const u32 qoff  = ((wm * 32 + (lane & 15)) * SKA + (lane >> 4) * 8) * 2;
    const u32 sboff = ((lane & 15) * SKA + (lane >> 4) * 8) * 2;
    const u32 vtoff = ((((lane >> 3) & 1) * 8 + (lane & 7)) * SKA + (lane >> 4) * 8) * 2;

    const int n_tiles = 2 * qt + 2;
    for (int kt = 0; kt < n_tiles; ++kt) {
        const int k0t = kt * 64;
        {   // load K/V tiles (64x64 fp16 each), 128 threads
            const int row = tid >> 1, c = (tid & 1) * 32;
            const size_t g = gb + (size_t)(k0t + row) * DH_ + c;
            const uint4* s0 = (const uint4*)(g_k + g);
            const uint4* s1 = (const uint4*)(g_v + g);
            uint4* d0 = (uint4*)(smK + row * SKA + c);
            uint4* d1 = (uint4*)(smV + row * SKA + c);
#pragma unroll
            for (int i = 0; i < 4; i++) { d0[i] = s0[i]; d1[i] = s1[i]; }
        }
        __syncthreads();

        if (k0t <= q0 + wm * 32 + 31) {   // warp-uniform: skip fully-masked tiles
            // ---- S = Q K^T for both m-tiles, f32 accum
            float s0[8][4] = {}, s1[8][4] = {};
#pragma unroll
            for (int ks = 0; ks < 4; ks++) {
                u32 qf0[4], qf1[4];
                ldmx4(qf0, sbQ + qoff + ks * 32);
                ldmx4(qf1, sbQ + qoff + 16 * SKA * 2 + ks * 32);
#pragma unroll
                for (int g = 0; g < 4; g++) {
                    u32 k4[4];
                    ldmx4(k4, sbK + sboff + g * 16 * SKA * 2 + ks * 32);
                    mma_f16(s0[2 * g],     qf0, k4[0], k4[2]);
                    mma_f16(s0[2 * g + 1], qf0, k4[1], k4[3]);
                    mma_f16(s1[2 * g],     qf1, k4[0], k4[2]);
                    mma_f16(s1[2 * g + 1], qf1, k4[1], k4[3]);
                }
            }

            // ---- causal mask (tiles crossing any of this warp's rows)
            if (k0t + 63 > q0 + wm * 32) {
#pragma unroll
                for (int b = 0; b < 8; b++) {
                    int cb = k0t + b * 8 + (lane & 3) * 2;
                    if (cb > r0)          s0[b][0] = -1e30f;
                    if (cb + 1 > r0)      s0[b][1] = -1e30f;
                    if (cb > r0 + 8)      s0[b][2] = -1e30f;
                    if (cb + 1 > r0 + 8)  s0[b][3] = -1e30f;
                    if (cb > r1)          s1[b][0] = -1e30f;
                    if (cb + 1 > r1)      s1[b][1] = -1e30f;
                    if (cb > r1 + 8)      s1[b][2] = -1e30f;
                    if (cb + 1 > r1 + 8)  s1[b][3] = -1e30f;
                }
            }

            // ---- online softmax (exp2 domain); packed-f16 quad max
            float tA0 = fmaxf(s0[0][0], s0[0][1]), tB0 = fmaxf(s0[0][2], s0[0][3]);
            float tA1 = fmaxf(s1[0][0], s1[0][1]), tB1 = fmaxf(s1[0][2], s1[0][3]);
#pragma unroll
            for (int b = 1; b < 8; b++) {
                tA0 = fmaxf(tA0, fmaxf(s0[b][0], s0[b][1]));
                tB0 = fmaxf(tB0, fmaxf(s0[b][2], s0[b][3]));
                tA1 = fmaxf(tA1, fmaxf(s1[b][0], s1[b][1]));
                tB1 = fmaxf(tB1, fmaxf(s1[b][2], s1[b][3]));
            }
            {
                __half2 m0h = __floats2half2_rn(tA0, tB0);
                __half2 m1h = __floats2half2_rn(tA1, tB1);
                m0h = __hmax2(m0h, __shfl_xor_sync(~0u, m0h, 1));
                m1h = __hmax2(m1h, __shfl_xor_sync(~0u, m1h, 1));
                m0h = __hmax2(m0h, __shfl_xor_sync(~0u, m0h, 2));
                m1h = __hmax2(m1h, __shfl_xor_sync(~0u, m1h, 2));
                float2 f0 = __half22float2(m0h), f1 = __half22float2(m1h);
                tA0 = f0.x; tB0 = f0.y; tA1 = f1.x; tB1 = f1.y;
            }
            float nA0 = fmaxf(mA0, tA0), nB0 = fmaxf(mB0, tB0);
            float nA1 = fmaxf(mA1, tA1), nB1 = fmaxf(mB1, tB1);
            float aA0 = ex2f(mA0 - nA0), aB0 = ex2f(mB0 - nB0);
            float aA1 = ex2f(mA1 - nA1), aB1 = ex2f(mB1 - nB1);
            mA0 = nA0; mB0 = nB0; mA1 = nA1; mB1 = nB1;
#pragma unroll
            for (int b = 0; b < 8; b++) {
                o0[b][0] *= aA0; o0[b][1] *= aA0;
                o0[b][2] *= aB0; o0[b][3] *= aB0;
                o1[b][0] *= aA1; o1[b][1] *= aA1;
                o1[b][2] *= aB1; o1[b][3] *= aB1;
            }

            // ---- P = exp2(S-m) fp16, PV per kstep; per-lane l partials
            float sA0 = 0.f, sB0 = 0.f, sA1 = 0.f, sB1 = 0.f;
#pragma unroll
            for (int ks = 0; ks < 4; ks++) {
                float p0[8], p1[8];
                p0[0] = ex2f(s0[2 * ks][0] - mA0);     p0[1] = ex2f(s0[2 * ks][1] - mA0);
                p0[2] = ex2f(s0[2 * ks][2] - mB0);     p0[3] = ex2f(s0[2 * ks][3] - mB0);
                p0[4] = ex2f(s0[2 * ks + 1][0] - mA0); p0[5] = ex2f(s0[2 * ks + 1][1] - mA0);
                p0[6] = ex2f(s0[2 * ks + 1][2] - mB0); p0[7] = ex2f(s0[2 * ks + 1][3] - mB0);
                p1[0] = ex2f(s1[2 * ks][0] - mA1);     p1[1] = ex2f(s1[2 * ks][1] - mA1);
                p1[2] = ex2f(s1[2 * ks][2] - mB1);     p1[3] = ex2f(s1[2 * ks][3] - mB1);
                p1[4] = ex2f(s1[2 * ks + 1][0] - mA1); p1[5] = ex2f(s1[2 * ks + 1][1] - mA1);
                p1[6] = ex2f(s1[2 * ks + 1][2] - mB1); p1[7] = ex2f(s1[2 * ks + 1][3] - mB1);
                sA0 += p0[0] + p0[1] + p0[4] + p0[5];
                sB0 += p0[2] + p0[3] + p0[6] + p0[7];
                sA1 += p1[0] + p1[1] + p1[4] + p1[5];
                sB1 += p1[2] + p1[3] + p1[6] + p1[7];
                u32 ph0[4], ph1[4];
                ph0[0] = pkhf(p0[0], p0[1]); ph0[1] = pkhf(p0[2], p0[3]);
                ph0[2] = pkhf(p0[4], p0[5]); ph0[3] = pkhf(p0[6], p0[7]);
                ph1[0] = pkhf(p1[0], p1[1]); ph1[1] = pkhf(p1[2], p1[3]);
                ph1[2] = pkhf(p1[4], p1[5]); ph1[3] = pkhf(p1[6], p1[7]);
#pragma unroll
                for (int g = 0; g < 4; g++) {
                    u32 v4[4];
                    ldmx4t(v4, sbV + vtoff + ks * 16 * SKA * 2 + g * 32);
                    mma_f16(o0[2 * g],     ph0, v4[0], v4[1]);
                    mma_f16(o0[2 * g + 1], ph0, v4[2], v4[3]);
                    mma_f16(o1[2 * g],     ph1, v4[0], v4[1]);
                    mma_f16(o1[2 * g + 1], ph1, v4[2], v4[3]);
                }
            }
            lA0 = lA0 * aA0 + sA0;  lB0 = lB0 * aB0 + sB0;
            lA1 = lA1 * aA1 + sA1;  lB1 = lB1 * aB1 + sB1;
        }
        __syncthreads();
    }

    // ---- final quad reduction of l, then write ctx fp16
    lA0 += __shfl_xor_sync(~0u, lA0, 1); lA0 += __shfl_xor_sync(~0u, lA0, 2);
    lB0 += __shfl_xor_sync(~0u, lB0, 1); lB0 += __shfl_xor_sync(~0u, lB0, 2);
    lA1 += __shfl_xor_sync(~0u, lA1, 1); lA1 += __shfl_xor_sync(~0u, lA1, 2);
    lB1 += __shfl_xor_sync(~0u, lB1, 1); lB1 += __shfl_xor_sync(~0u, lB1, 2);
    const float iA0 = 1.0f / lA0, iB0 = 1.0f / lB0;
    const float iA1 = 1.0f / lA1, iB1 = 1.0f / lB1;
    const int bb = bh >> 4, hh = bh & 15;
    const size_t m0r = (size_t)(bb * S_ + r0) * D_ + hh * 64;
#pragma unroll
    for (int b = 0; b < 8; b++) {
        int col = b * 8 + (lane & 3) * 2;
        *(u32*)(g_cx + m0r + col)            = pkhf(o0[b][0] * iA0, o0[b][1] * iA0);
        *(u32*)(g_cx + m0r + 8 * D_ + col)   = pkhf(o0[b][2] * iB0, o0[b][3] * iB0);
        *(u32*)(g_cx + m0r + 16 * D_ + col)  = pkhf(o1[b][0] * iA1, o1[b][1] * iA1);
        *(u32*)(g_cx + m0r + 24 * D_ + col)  = pkhf(o1[b][2] * iB1, o1[b][3] * iB1);
    }
}

// =================================================================
// LayerNorm over last dim (1024)
// =================================================================
__global__ __launch_bounds__(256) void ln_kernel(
    const float* __restrict__ gamma,
    const float* __restrict__ beta,
    float* __restrict__ out)
{
    __shared__ float ws[8], wq2[8];
    const int row = blockIdx.x;
    const int t = threadIdx.x;
    const int lane = t & 31, w = t >> 5;
    const float* rp = g_res + (size_t)row * D_;

    float4 v = *(const float4*)(rp + t * 4);
    float s = v.x + v.y + v.z + v.w;
    float q = v.x * v.x + v.y * v.y + v.z * v.z + v.w * v.w;
#pragma unroll
    for (int o = 16; o > 0; o >>= 1) {
        s += __shfl_xor_sync(0xffffffffu, s, o);
        q += __shfl_xor_sync(0xffffffffu, q, o);
    }
    if (lane == 0) { ws[w] = s; wq2[w] = q; }
    __syncthreads();
    float S = 0.f, Q = 0.f;
#pragma unroll
    for (int i = 0; i < 8; i++) { S += ws[i]; Q += wq2[i]; }

    float mu  = S * (1.0f / 1024.0f);
    float var = Q * (1.0f / 1024.0f) - mu * mu;
    float rstd = rsqrtf(var + 1e-5f);

    float4 g  = *(const float4*)(gamma + t * 4);
    float4 bt = *(const float4*)(beta  + t * 4);
    float4 o4;
    o4.x = (v.x - mu) * rstd * g.x + bt.x;
    o4.y = (v.y - mu) * rstd * g.y + bt.y;
    o4.z = (v.z - mu) * rstd * g.z + bt.z;
    o4.w = (v.w - mu) * rstd * g.w + bt.w;
    *(float4*)(out + (size_t)row * D_ + t * 4) = o4;
}

// =================================================================
extern "C" void kernel_launch(void* const* d_in, const int* in_sizes, int n_in,
                              void* d_out, int out_size)
{
    const float* x     = (const float*)d_in[0];
    const float* wq    = (const float*)d_in[1];
    const float* wk    = (const float*)d_in[2];
    const float* wv    = (const float*)d_in[3];
    const float* wo    = (const float*)d_in[4];
    const float* gamma = (const float*)d_in[5];
    const float* beta  = (const float*)d_in[6];
    float* out = (float*)d_out;

    const int gemm_smem = 2 * STAGE_BYTES;   // 40 KB double-buffered
    cudaFuncSetAttribute(qkv_hmma,
                         cudaFuncAttributeMaxDynamicSharedMemorySize, gemm_smem);
    cudaFuncSetAttribute(proj_hmma,
                         cudaFuncAttributeMaxDynamicSharedMemorySize, gemm_smem);

    cvt_x<<<M_, 256>>>(x);
    wt_t<<<dim3(32, 128), dim3(32, 8)>>>(wq, wk, wv, wo);
    qkv_hmma<<<dim3(M_ / 128, 3072 / 128), 256, gemm_smem>>>();
    attn_hmma<<<dim3(S_ / 128, B_ * H_), 128>>>();
    proj_hmma<<<dim3(M_ / 128, D_ / 128), 256, gemm_smem>>>(x);
    ln_kernel<<<M_, 256>>>(gamma, beta, out);
}